// round 11
// baseline (speedup 1.0000x reference)
#include <cuda_runtime.h>

// ---------------------------------------------------------------------------
// ReservoirLinearRNN — only the LAST timestep feeds the output.
// h_last = sum_{k<256} U_k A^k   (K=256 truncation, ||A^k||=0.95^k, err ~1e-6)
// Binary combine tree: V_{l+1}[j] = V_l[2j] + V_l[2j+1] @ M_l,  M_l = A^(2^l).
// Each level: fused [M_{l+1}=M_l^2] + [V_{l+1}=combine(V_l,M_l)] in ONE launch.
// R10/R11: k_lvl microkernel -> 128 threads, 8x4 accumulators (FMA:LDS 32:3
// per thread-step, FMA-bound), double-buffered smem, 1 barrier/tile.
// All GEMMs are K-split (z=2) writing partial halves; consumers sum halves.
// ---------------------------------------------------------------------------

namespace {
constexpr int HN  = 512;
constexpr int TT  = 2048;
constexpr int LL  = 128;
constexpr int MMc = 256;
constexpr int FF  = 1024;
constexpr int MSZ = HN * HN;      // 262144 floats
}

// Scratch (device globals only — no allocations)
__device__ float g_Weff[LL * HN];
__device__ float g_beff[HN];
__device__ float g_Va[4096 * HN];          // V0: rows m = k*16 + b (k = lag)
__device__ float g_V1[2 * 2048 * HN];      // ping
__device__ float g_V2[2 * 1024 * HN];      // pong
__device__ float g_M[7 * 2 * MSZ];         // M1..M7, each as 2 K-split halves
__device__ float g_zn[16 * HN];
__device__ float g_t1[16 * FF];

// --------------------------- init: Weff = We@Wb, beff = be@Wb ---------------
__global__ void k_init(const float* __restrict__ We, const float* __restrict__ be,
                       const float* __restrict__ Wb) {
    const int nWeff = LL * HN;
    const int total = nWeff + HN;
    for (int id = blockIdx.x * blockDim.x + threadIdx.x; id < total;
         id += gridDim.x * blockDim.x) {
        if (id < nWeff) {
            int l = id / HN, h = id % HN;
            float acc = 0.f;
            for (int m = 0; m < MMc; m++) acc += We[l * MMc + m] * Wb[m * HN + h];
            g_Weff[id] = acc;
        } else {
            int h = id - nWeff;
            float acc = 0.f;
            for (int m = 0; m < MMc; m++) acc += be[m] * Wb[m * HN + h];
            g_beff[h] = acc;
        }
    }
}

// --------------------------- V0 = Bu window GEMM -----------------------------
// row m = k*16 + b  ->  x[b, 2047-k, :] @ Weff + beff     (4096 x 512)
__global__ __launch_bounds__(256) void k_bu(const float* __restrict__ x) {
    __shared__ float As[32][64];
    __shared__ float Bs[32][64];
    int t  = threadIdx.x;
    int m0 = blockIdx.x * 64, n0 = blockIdx.y * 64;
    int r  = t >> 2, c0 = (t & 3) * 8;
    int m  = m0 + r;
    int k  = m >> 4, b = m & 15;
    int tt = (TT - 1) - k;
    const float* xrow = x + ((size_t)(b * TT + tt)) * LL;
    int rb = t >> 3, cb = (t & 7) * 8;
    int tx = t & 15, ty = t >> 4;
    float acc[4][4] = {};
    for (int k0 = 0; k0 < LL; k0 += 32) {
        float4 v0 = *(const float4*)(xrow + k0 + c0);
        float4 v1 = *(const float4*)(xrow + k0 + c0 + 4);
        As[c0 + 0][r] = v0.x; As[c0 + 1][r] = v0.y; As[c0 + 2][r] = v0.z; As[c0 + 3][r] = v0.w;
        As[c0 + 4][r] = v1.x; As[c0 + 5][r] = v1.y; As[c0 + 6][r] = v1.z; As[c0 + 7][r] = v1.w;
        const float* bp = g_Weff + (size_t)(k0 + rb) * HN + n0 + cb;
        *(float4*)&Bs[rb][cb]     = *(const float4*)bp;
        *(float4*)&Bs[rb][cb + 4] = *(const float4*)(bp + 4);
        __syncthreads();
#pragma unroll
        for (int kk = 0; kk < 32; kk++) {
            float4 a4 = *(const float4*)&As[kk][ty * 4];
            float4 b4 = *(const float4*)&Bs[kk][tx * 4];
            acc[0][0] += a4.x * b4.x; acc[0][1] += a4.x * b4.y; acc[0][2] += a4.x * b4.z; acc[0][3] += a4.x * b4.w;
            acc[1][0] += a4.y * b4.x; acc[1][1] += a4.y * b4.y; acc[1][2] += a4.y * b4.z; acc[1][3] += a4.y * b4.w;
            acc[2][0] += a4.z * b4.x; acc[2][1] += a4.z * b4.y; acc[2][2] += a4.z * b4.z; acc[2][3] += a4.z * b4.w;
            acc[3][0] += a4.w * b4.x; acc[3][1] += a4.w * b4.y; acc[3][2] += a4.w * b4.z; acc[3][3] += a4.w * b4.w;
        }
        __syncthreads();
    }
#pragma unroll
    for (int i = 0; i < 4; i++) {
        int col = n0 + tx * 4;
        float4 v;
        v.x = acc[i][0] + g_beff[col + 0];
        v.y = acc[i][1] + g_beff[col + 1];
        v.z = acc[i][2] + g_beff[col + 2];
        v.w = acc[i][3] + g_beff[col + 3];
        *(float4*)&g_Va[(size_t)(m0 + ty * 4 + i) * HN + col] = v;
    }
}

// --------------------------- fused level kernel ------------------------------
// blocks [0, nSq):        M_{l+1} partial = (m0+m1)[64-tile] @ (m0+m1), K-half z
// blocks [nSq, nSq+gx*16): V_{l+1} partial = V_l[odd] @ (m0+m1), + even fold
// 128 threads; 64x64 tile; 8x4 accumulators; double-buffered smem.
__global__ __launch_bounds__(128) void k_lvl(const float* __restrict__ vin, int vhoff,
                                             const float* __restrict__ m0p,
                                             const float* __restrict__ m1p,
                                             float* __restrict__ vout, int rows_out,
                                             float* __restrict__ mout, int nSq) {
    __shared__ float As[2][32][64];
    __shared__ float Bs[2][32][64];
    int bid = blockIdx.x;
    bool isSq = bid < nSq;
    int gx = (rows_out + 63) >> 6;
    int bx, by, bz;
    if (isSq) {
        bx = bid & 7; by = (bid >> 3) & 7; bz = bid >> 6;
    } else {
        int vb = bid - nSq;
        bx = vb % gx; vb /= gx;
        by = vb & 7;  bz = vb >> 3;
    }
    int t  = threadIdx.x;                // 0..127
    int mt = bx * 64, n0 = by * 64;
    int kbeg = bz * 256;
    int ar  = t >> 1, ac0 = (t & 1) * 16;   // A load: row ar, k-cols [ac0, ac0+16)
    int brw = t >> 2, bc0 = (t & 3) * 16;   // B load: k-row brw, n-cols [bc0, bc0+16)
    int tx = t & 15, ty = t >> 4;           // compute: cols tx*4.., rows ty*8..

    const float* arow;
    const float* arow2 = nullptr;
    if (isSq) {
        arow = m0p + (size_t)(mt + ar) * HN;
        if (m1p) arow2 = m1p + (size_t)(mt + ar) * HN;
    } else {
        int gr = mt + ar;
        if (gr >= rows_out) gr = rows_out - 1;
        arow = vin + (size_t)(32 * (gr >> 4) + 16 + (gr & 15)) * HN;  // odd source row
        if (vhoff) arow2 = arow + vhoff;
    }

    float4 pa[4], pb[4];
    auto loadAB = [&](int k0) {
#pragma unroll
        for (int i = 0; i < 4; i++)
            pa[i] = *(const float4*)(arow + k0 + ac0 + 4 * i);
        if (arow2) {
#pragma unroll
            for (int i = 0; i < 4; i++) {
                float4 w = *(const float4*)(arow2 + k0 + ac0 + 4 * i);
                pa[i].x += w.x; pa[i].y += w.y; pa[i].z += w.z; pa[i].w += w.w;
            }
        }
        size_t boff = (size_t)(k0 + brw) * HN + n0 + bc0;
#pragma unroll
        for (int i = 0; i < 4; i++)
            pb[i] = *(const float4*)(m0p + boff + 4 * i);
        if (m1p) {
#pragma unroll
            for (int i = 0; i < 4; i++) {
                float4 w = *(const float4*)(m1p + boff + 4 * i);
                pb[i].x += w.x; pb[i].y += w.y; pb[i].z += w.z; pb[i].w += w.w;
            }
        }
    };
    auto stash = [&](int buf) {
#pragma unroll
        for (int i = 0; i < 4; i++) {
            As[buf][ac0 + 4 * i + 0][ar] = pa[i].x;
            As[buf][ac0 + 4 * i + 1][ar] = pa[i].y;
            As[buf][ac0 + 4 * i + 2][ar] = pa[i].z;
            As[buf][ac0 + 4 * i + 3][ar] = pa[i].w;
            *(float4*)&Bs[buf][brw][bc0 + 4 * i] = pb[i];
        }
    };

    float acc[8][4] = {};
    loadAB(kbeg);
    stash(0);
    __syncthreads();

    int buf = 0;
    const int kend = kbeg + 256;
#pragma unroll 1
    for (int k0 = kbeg; k0 < kend; k0 += 32) {
        bool has = (k0 + 32) < kend;
        if (has) loadAB(k0 + 32);
#pragma unroll
        for (int kk = 0; kk < 32; kk++) {
            float4 b4 = *(const float4*)&Bs[buf][kk][tx * 4];
            float4 a0 = *(const float4*)&As[buf][kk][ty * 8];
            float4 a1 = *(const float4*)&As[buf][kk][ty * 8 + 4];
            acc[0][0] += a0.x * b4.x; acc[0][1] += a0.x * b4.y; acc[0][2] += a0.x * b4.z; acc[0][3] += a0.x * b4.w;
            acc[1][0] += a0.y * b4.x; acc[1][1] += a0.y * b4.y; acc[1][2] += a0.y * b4.z; acc[1][3] += a0.y * b4.w;
            acc[2][0] += a0.z * b4.x; acc[2][1] += a0.z * b4.y; acc[2][2] += a0.z * b4.z; acc[2][3] += a0.z * b4.w;
            acc[3][0] += a0.w * b4.x; acc[3][1] += a0.w * b4.y; acc[3][2] += a0.w * b4.z; acc[3][3] += a0.w * b4.w;
            acc[4][0] += a1.x * b4.x; acc[4][1] += a1.x * b4.y; acc[4][2] += a1.x * b4.z; acc[4][3] += a1.x * b4.w;
            acc[5][0] += a1.y * b4.x; acc[5][1] += a1.y * b4.y; acc[5][2] += a1.y * b4.z; acc[5][3] += a1.y * b4.w;
            acc[6][0] += a1.z * b4.x; acc[6][1] += a1.z * b4.y; acc[6][2] += a1.z * b4.z; acc[6][3] += a1.z * b4.w;
            acc[7][0] += a1.w * b4.x; acc[7][1] += a1.w * b4.y; acc[7][2] += a1.w * b4.z; acc[7][3] += a1.w * b4.w;
        }
        if (has) stash(buf ^ 1);
        __syncthreads();
        buf ^= 1;
    }

    if (isSq) {
        float* cz = mout + (size_t)bz * MSZ;
#pragma unroll
        for (int i = 0; i < 8; i++) {
            float4 v = {acc[i][0], acc[i][1], acc[i][2], acc[i][3]};
            *(float4*)&cz[(size_t)(mt + ty * 8 + i) * HN + n0 + tx * 4] = v;
        }
    } else {
        float* cz = vout + (size_t)bz * rows_out * HN;
#pragma unroll
        for (int i = 0; i < 8; i++) {
            int mo = mt + ty * 8 + i;
            if (mo >= rows_out) break;
            int col = n0 + tx * 4;
            float4 v = {acc[i][0], acc[i][1], acc[i][2], acc[i][3]};
            if (bz == 0) {                  // fold even term into half 0
                const float* ev = vin + (size_t)(32 * (mo >> 4) + (mo & 15)) * HN + col;
                float4 e = *(const float4*)ev;
                if (vhoff) {
                    float4 e2 = *(const float4*)(ev + vhoff);
                    e.x += e2.x; e.y += e2.y; e.z += e2.z; e.w += e2.w;
                }
                v.x += e.x; v.y += e.y; v.z += e.z; v.w += e.w;
            }
            *(float4*)&cz[(size_t)mo * HN + col] = v;
        }
    }
}

// --------------------------- z_last + layernorm -----------------------------
__global__ void k_ln(const float* __restrict__ x, const float* __restrict__ Wr,
                     const float* __restrict__ br, const float* __restrict__ lg,
                     const float* __restrict__ lb) {
    int b = blockIdx.x, j = threadIdx.x;    // 512 threads
    __shared__ float xs[LL];
    __shared__ float red[HN];
    if (j < LL) xs[j] = x[(size_t)(b * TT + (TT - 1)) * LL + j];
    __syncthreads();
    float hv = g_V2[(size_t)b * HN + j] + g_V2[16 * HN + (size_t)b * HN + j];
    float acc = br[j];
#pragma unroll 8
    for (int l = 0; l < LL; l++) acc += xs[l] * Wr[(size_t)l * HN + j];
    float z = hv + acc;
    red[j] = z; __syncthreads();
    for (int off = 256; off > 0; off >>= 1) {
        if (j < off) red[j] += red[j + off];
        __syncthreads();
    }
    float mu = red[0] / (float)HN;
    __syncthreads();
    float d = z - mu;
    red[j] = d * d; __syncthreads();
    for (int off = 256; off > 0; off >>= 1) {
        if (j < off) red[j] += red[j + off];
        __syncthreads();
    }
    float var = red[0] / (float)HN;
    g_zn[(size_t)b * HN + j] = d * rsqrtf(var + 1e-5f) * lg[j] + lb[j];
}

// --------------------------- MLP --------------------------------------------
__global__ void k_mlp1(const float* __restrict__ W1, const float* __restrict__ b1) {
    int b = blockIdx.x;
    int f = blockIdx.y * 128 + threadIdx.x;
    __shared__ float zs[HN];
    for (int i = threadIdx.x; i < HN; i += 128) zs[i] = g_zn[(size_t)b * HN + i];
    __syncthreads();
    float acc = b1[f];
#pragma unroll 8
    for (int j = 0; j < HN; j++) acc += zs[j] * W1[(size_t)j * FF + f];
    g_t1[(size_t)b * FF + f] = fmaxf(acc, 0.f);
}

__global__ void k_mlp2(const float* __restrict__ W2, const float* __restrict__ b2,
                       float* __restrict__ out) {
    int b = blockIdx.x;
    int j = blockIdx.y * 128 + threadIdx.x;
    __shared__ float ts[FF];
    for (int i = threadIdx.x; i < FF; i += 128) ts[i] = g_t1[(size_t)b * FF + i];
    __syncthreads();
    float acc = b2[j];
#pragma unroll 8
    for (int f = 0; f < FF; f++) acc += ts[f] * W2[(size_t)f * HN + j];
    out[(size_t)b * HN + j] = acc;
}

// --------------------------- launch -----------------------------------------
extern "C" void kernel_launch(void* const* d_in, const int* in_sizes, int n_in,
                              void* d_out, int out_size) {
    const float* x  = (const float*)d_in[0];
    const float* We = (const float*)d_in[1];
    const float* be = (const float*)d_in[2];
    const float* Wb = (const float*)d_in[3];
    const float* A  = (const float*)d_in[4];
    const float* Wr = (const float*)d_in[5];
    const float* br = (const float*)d_in[6];
    const float* lg = (const float*)d_in[7];
    const float* lb = (const float*)d_in[8];
    const float* W1 = (const float*)d_in[9];
    const float* b1 = (const float*)d_in[10];
    const float* W2 = (const float*)d_in[11];
    const float* b2 = (const float*)d_in[12];
    float* out = (float*)d_out;

    static float* gM = nullptr; static float* gV1 = nullptr; static float* gV2 = nullptr;
    static float* gVa = nullptr;
    if (!gM)  cudaGetSymbolAddress((void**)&gM,  g_M);
    if (!gV1) cudaGetSymbolAddress((void**)&gV1, g_V1);
    if (!gV2) cudaGetSymbolAddress((void**)&gV2, g_V2);
    if (!gVa) cudaGetSymbolAddress((void**)&gVa, g_Va);
    float* M[8];
    for (int l = 1; l <= 7; l++) M[l] = gM + (size_t)(l - 1) * 2 * MSZ;

    k_init<<<258, 256>>>(We, be, Wb);
    k_bu<<<dim3(64, 8), 256>>>(x);

    // Level l: fused [sq: M_{l+1} = M_l^2] + [vec: V_{l+1} = combine(V_l, M_l)]
    // grid = 128 sq blocks + ceil(rows_out/64)*16 vec blocks ; 128 threads each
    k_lvl<<<128 + 32 * 16, 128>>>(gVa, 0,          A,    nullptr,    gV1, 2048, M[1], 128);
    k_lvl<<<128 + 16 * 16, 128>>>(gV1, 2048 * HN,  M[1], M[1] + MSZ, gV2, 1024, M[2], 128);
    k_lvl<<<128 +  8 * 16, 128>>>(gV2, 1024 * HN,  M[2], M[2] + MSZ, gV1,  512, M[3], 128);
    k_lvl<<<128 +  4 * 16, 128>>>(gV1,  512 * HN,  M[3], M[3] + MSZ, gV2,  256, M[4], 128);
    k_lvl<<<128 +  2 * 16, 128>>>(gV2,  256 * HN,  M[4], M[4] + MSZ, gV1,  128, M[5], 128);
    k_lvl<<<128 +  1 * 16, 128>>>(gV1,  128 * HN,  M[5], M[5] + MSZ, gV2,   64, M[6], 128);
    k_lvl<<<128 +  1 * 16, 128>>>(gV2,   64 * HN,  M[6], M[6] + MSZ, gV1,   32, M[7], 128);
    k_lvl<<<        1 * 16, 128>>>(gV1,  32 * HN,  M[7], M[7] + MSZ, gV2,   16, nullptr, 0);

    k_ln<<<16, 512>>>(x, Wr, br, lg, lb);
    k_mlp1<<<dim3(16, 8), 128>>>(W1, b1);
    k_mlp2<<<dim3(16, 4), 128>>>(W2, b2, out);
}